// round 7
// baseline (speedup 1.0000x reference)
#include <cuda_runtime.h>
#include <cstdint>

// Problem constants
#define B_ROWS   65536
#define C_COLS   300
#define A_DIM    32
#define XSTRIDE  600

#define THREADS  256
#define NWARPS   8
#define GROUP    64                      // rows per CTA group
#define NGROUPS  (B_ROWS / GROUP)        // 1024
#define GRID     148

#define IDXCAP   40                      // nonzero-option cap (mean ~16, sd 3.8)

// SMEM: cards[64][300] f32 | ap[64][32] | per-warp {idx[40], sc[40], pad}
#define CARDS_FLOATS (GROUP * C_COLS)                 // 19200
#define AP_FLOATS    (GROUP * A_DIM)                  // 2048
#define PW_WORDS     96                               // idx 40 + sc 40 + pad 16
#define SMEM_FLOATS  (CARDS_FLOATS + AP_FLOATS + NWARPS * PW_WORDS)  // 22016
#define SMEM_BYTES   (SMEM_FLOATS * 4)                // 88064 -> 2 CTAs/SM

__device__ __forceinline__ void fma2(unsigned long long& d,
                                     unsigned long long a,
                                     unsigned long long b) {
    asm("fma.rn.f32x2 %0, %1, %2, %0;" : "+l"(d) : "l"(a), "l"(b));
}
__device__ __forceinline__ float2 unpack2(unsigned long long v) {
    float2 r;
    asm("mov.b64 {%0, %1}, %2;" : "=f"(r.x), "=f"(r.y) : "l"(v));
    return r;
}
__device__ __forceinline__ unsigned long long dup2(float v) {
    unsigned long long r;
    asm("mov.b64 %0, {%1, %1};" : "=l"(r) : "f"(v));
    return r;
}
__device__ __forceinline__ void cp16(uint32_t saddr, const float* gaddr) {
    asm volatile("cp.async.cg.shared.global [%0], [%1], 16;" :: "r"(saddr), "l"(gaddr));
}
__device__ __forceinline__ void cp_commit() { asm volatile("cp.async.commit_group;"); }
__device__ __forceinline__ void cp_wait0()  { asm volatile("cp.async.wait_group 0;"); }

__global__ __launch_bounds__(THREADS, 2)
void draftbot_kernel(const float* __restrict__ X,
                     const float* __restrict__ W,
                     float* __restrict__ Out)
{
    extern __shared__ float smem[];
    float* cards = smem;                            // [64][300]
    float* apbuf = smem + CARDS_FLOATS;             // [64][32]
    const int tid  = threadIdx.x;
    const int lane = tid & 31;
    const int warp = tid >> 5;
    float* pw    = smem + CARDS_FLOATS + AP_FLOATS + warp * PW_WORDS;
    int*   widx  = (int*)pw;                        // [40]
    float* scw   = pw + IDXCAP;                     // [40]

    const uint32_t cards_u32 = (uint32_t)__cvta_generic_to_shared(cards);

    const unsigned FULL   = 0xffffffffu;
    const unsigned ltmask = (1u << lane) - 1u;
    const int ty = tid >> 3, tx = tid & 7;          // phase-1 tile: 2 rows x 4 a
    const int r0 = ty * 2;
    const int a0 = tx * 4;
    const int qid = lane >> 3;                      // phase-2 octets
    const int sub = lane & 7;

    int g = blockIdx.x;

    // prologue stage of group g
    if (g < NGROUPS) {
        const float* gb = X + (size_t)g * GROUP * XSTRIDE + C_COLS;
        #pragma unroll 1
        for (int t = 0; t < 19; t++) {
            int idx = tid + THREADS * t;            // 0..4863; valid < 4800
            if (idx < GROUP * 75) {
                int row = idx / 75, ch = idx - row * 75;
                cp16(cards_u32 + (uint32_t)(row * C_COLS + ch * 4) * 4,
                     gb + (size_t)row * XSTRIDE + ch * 4);
            }
        }
    }
    cp_commit();

    for (; g < NGROUPS; g += GRID) {
        cp_wait0();
        __syncthreads();                            // cards ready; prev phase-2 done

        // ---------- phase 1: ap = cards @ W + 1  (register-blocked 2r x 4a) ----------
        {
            unsigned long long acc00 = 0, acc01 = 0, acc10 = 0, acc11 = 0;
            const float* cb = cards + r0 * C_COLS;
            #pragma unroll 2
            for (int q = 0; q < 75; q++) {
                float4 c0 = *(const float4*)(cb + 4 * q);
                float4 c1 = *(const float4*)(cb + C_COLS + 4 * q);
                ulonglong2 w0 = *(const ulonglong2*)(W + (4 * q + 0) * A_DIM + a0);
                ulonglong2 w1 = *(const ulonglong2*)(W + (4 * q + 1) * A_DIM + a0);
                ulonglong2 w2 = *(const ulonglong2*)(W + (4 * q + 2) * A_DIM + a0);
                ulonglong2 w3 = *(const ulonglong2*)(W + (4 * q + 3) * A_DIM + a0);
                unsigned long long d;
                d = dup2(c0.x); fma2(acc00, d, w0.x); fma2(acc01, d, w0.y);
                d = dup2(c1.x); fma2(acc10, d, w0.x); fma2(acc11, d, w0.y);
                d = dup2(c0.y); fma2(acc00, d, w1.x); fma2(acc01, d, w1.y);
                d = dup2(c1.y); fma2(acc10, d, w1.x); fma2(acc11, d, w1.y);
                d = dup2(c0.z); fma2(acc00, d, w2.x); fma2(acc01, d, w2.y);
                d = dup2(c1.z); fma2(acc10, d, w2.x); fma2(acc11, d, w2.y);
                d = dup2(c0.w); fma2(acc00, d, w3.x); fma2(acc01, d, w3.y);
                d = dup2(c1.w); fma2(acc10, d, w3.x); fma2(acc11, d, w3.y);
            }
            float2 p0 = unpack2(acc00), p1 = unpack2(acc01);
            float2 p2 = unpack2(acc10), p3 = unpack2(acc11);
            *(float4*)(apbuf + r0 * A_DIM + a0) =
                make_float4(p0.x + 1.f, p0.y + 1.f, p1.x + 1.f, p1.y + 1.f);
            *(float4*)(apbuf + (r0 + 1) * A_DIM + a0) =
                make_float4(p2.x + 1.f, p2.y + 1.f, p3.x + 1.f, p3.y + 1.f);
        }
        __syncthreads();                            // ap ready; cards free

        // prefetch next group's cards, overlapping phase 2
        if (g + GRID < NGROUPS) {
            const float* gb = X + (size_t)(g + GRID) * GROUP * XSTRIDE + C_COLS;
            #pragma unroll 1
            for (int t = 0; t < 19; t++) {
                int idx = tid + THREADS * t;
                if (idx < GROUP * 75) {
                    int row = idx / 75, ch = idx - row * 75;
                    cp16(cards_u32 + (uint32_t)(row * C_COLS + ch * 4) * 4,
                         gb + (size_t)row * XSTRIDE + ch * 4);
                }
            }
        }
        cp_commit();

        // ---------- phase 2: per-warp rows, sparse scores + masked log-softmax ----------
        const int growbase = g * GROUP + warp * 8;
        #pragma unroll 1
        for (int lr8 = 0; lr8 < 8; lr8++) {
            const int lrow = warp * 8 + lr8;        // group-local row
            const int grow = growbase + lr8;        // global row

            // compaction of nonzero option columns (batched loads for MLP)
            const float4* osrc = (const float4*)(X + (size_t)grow * XSTRIDE);
            float4 ovv[3];
            ovv[0] = osrc[lane];                    // lane < 75 always (lane<=31)
            ovv[1] = (lane + 32 < 75) ? osrc[lane + 32] : make_float4(0,0,0,0);
            ovv[2] = (lane + 64 < 75) ? osrc[lane + 64] : make_float4(0,0,0,0);
            int cn = 0;
            #pragma unroll
            for (int t = 0; t < 3; t++) {
                float vals[4] = {ovv[t].x, ovv[t].y, ovv[t].z, ovv[t].w};
                #pragma unroll
                for (int i = 0; i < 4; i++) {
                    bool f = (vals[i] != 0.0f);
                    unsigned mm = __ballot_sync(FULL, f);
                    if (f) {
                        int pos = cn + __popc(mm & ltmask);
                        if (pos < IDXCAP) widx[pos] = 4 * (lane + 32 * t) + i;
                    }
                    cn += __popc(mm);
                }
            }
            if (cn > IDXCAP) cn = IDXCAP;
            __syncwarp();

            // scores: 8 lanes per column, 4 columns in flight
            float4 av = ((const float4*)(apbuf + lrow * A_DIM))[sub];
            const int nch = (cn + 3) >> 2;
            #pragma unroll 2
            for (int ch = 0; ch < nch; ch++) {
                int  j   = ch * 4 + qid;
                bool val = j < cn;
                int  c   = val ? widx[j] : 0;
                float4 wv = *(const float4*)(W + c * A_DIM + sub * 4);
                float p = av.x * wv.x + av.y * wv.y + av.z * wv.z + av.w * wv.w;
                p += __shfl_xor_sync(FULL, p, 1);
                p += __shfl_xor_sync(FULL, p, 2);
                p += __shfl_xor_sync(FULL, p, 4);
                if (val && sub == 0) scw[j] = p;
            }
            __syncwarp();

            // masked log-softmax (zeros always present in the row)
            int  j0 = lane, j1 = lane + 32;
            bool v0 = j0 < cn, v1 = j1 < cn;
            float s0 = v0 ? scw[j0] : 0.0f;
            float s1 = v1 ? scw[j1] : 0.0f;
            int   c0 = v0 ? widx[j0] : -1;
            int   c1 = v1 ? widx[j1] : -1;

            float m = fmaxf(fmaxf(s0, s1), 0.0f);
            #pragma unroll
            for (int o = 16; o > 0; o >>= 1) m = fmaxf(m, __shfl_xor_sync(FULL, m, o));

            float g0 = (s0 > 0.f) ? 1.f : ((s0 < 0.f) ? -1.f : 0.f);
            float g1 = (s1 > 0.f) ? 1.f : ((s1 < 0.f) ? -1.f : 0.f);
            float sum = g0 * __expf(s0 - m * g0) + g1 * __expf(s1 - m * g1);
            #pragma unroll
            for (int o = 16; o > 0; o >>= 1) sum += __shfl_xor_sync(FULL, sum, o);
            float lse = __logf(sum);

            float* orow = Out + (size_t)grow * C_COLS;
            #pragma unroll
            for (int t = 0; t < 3; t++) {
                int gi = lane + 32 * t;
                if (gi < 75) *(float4*)(orow + 4 * gi) = make_float4(0.f, 0.f, 0.f, 0.f);
            }
            __syncwarp();
            if (c0 >= 0) orow[c0] = g0 * ((s0 - m * g0) - lse);
            if (c1 >= 0) orow[c1] = g1 * ((s1 - m * g1) - lse);
            __syncwarp();
        }
    }
}

extern "C" void kernel_launch(void* const* d_in, const int* in_sizes, int n_in,
                              void* d_out, int out_size)
{
    const float* X = (const float*)d_in[0];
    const float* W = (const float*)d_in[1];
    if (n_in >= 2 && in_sizes[0] < in_sizes[1]) {   // defensively order by size
        const float* t = X; X = W; W = t;
    }
    float* Out = (float*)d_out;

    cudaFuncSetAttribute(draftbot_kernel,
                         cudaFuncAttributeMaxDynamicSharedMemorySize, SMEM_BYTES);
    draftbot_kernel<<<GRID, THREADS, SMEM_BYTES>>>(X, W, Out);
}

// round 8
// speedup vs baseline: 2.0844x; 2.0844x over previous
#include <cuda_runtime.h>
#include <cstdint>

// Problem constants
#define B_ROWS   65536
#define C_COLS   300
#define A_DIM    32
#define XSTRIDE  600

#define THREADS  256
#define NWARPS   8
#define GROUP    32                      // rows per CTA group
#define NGROUPS  (B_ROWS / GROUP)        // 2048
#define GRID     296                     // 2 CTAs/SM

#define IDXCAP   40

#define WSTR     40                      // W_s row stride (floats): banks 8t+g distinct
#define CS       300                     // cards_s row stride: banks 12g+t distinct
#define APS      36                      // ap_s row stride

#define WS_FLOATS    (C_COLS * WSTR)     // 12000
#define CARDS_FLOATS (GROUP * CS)        // 9600
#define AP_FLOATS    (GROUP * APS)       // 1152
#define PW_WORDS     96
#define SMEM_FLOATS  (WS_FLOATS + CARDS_FLOATS + AP_FLOATS + NWARPS * PW_WORDS) // 23520
#define SMEM_BYTES   (SMEM_FLOATS * 4)   // 94080 -> 2 CTAs/SM

__device__ __forceinline__ uint32_t f2tf32(float f) {
    uint32_t r;
    asm("cvt.rna.tf32.f32 %0, %1;" : "=r"(r) : "f"(f));
    return r;
}
__device__ __forceinline__ void mma_k8(float& d0, float& d1, float& d2, float& d3,
                                       uint32_t a0, uint32_t a1, uint32_t a2, uint32_t a3,
                                       uint32_t b0, uint32_t b1) {
    asm("mma.sync.aligned.m16n8k8.row.col.f32.tf32.tf32.f32 "
        "{%0,%1,%2,%3},{%4,%5,%6,%7},{%8,%9},{%0,%1,%2,%3};"
        : "+f"(d0), "+f"(d1), "+f"(d2), "+f"(d3)
        : "r"(a0), "r"(a1), "r"(a2), "r"(a3), "r"(b0), "r"(b1));
}
__device__ __forceinline__ void mma_k4(float& d0, float& d1, float& d2, float& d3,
                                       uint32_t a0, uint32_t a1, uint32_t b0) {
    asm("mma.sync.aligned.m16n8k4.row.col.f32.tf32.tf32.f32 "
        "{%0,%1,%2,%3},{%4,%5},{%6},{%0,%1,%2,%3};"
        : "+f"(d0), "+f"(d1), "+f"(d2), "+f"(d3)
        : "r"(a0), "r"(a1), "r"(b0));
}
__device__ __forceinline__ void cp16(uint32_t saddr, const float* gaddr) {
    asm volatile("cp.async.cg.shared.global [%0], [%1], 16;" :: "r"(saddr), "l"(gaddr));
}
__device__ __forceinline__ void cp_commit() { asm volatile("cp.async.commit_group;"); }
__device__ __forceinline__ void cp_wait0()  { asm volatile("cp.async.wait_group 0;"); }

__global__ __launch_bounds__(THREADS, 2)
void draftbot_kernel(const float* __restrict__ X,
                     const float* __restrict__ W,
                     float* __restrict__ Out)
{
    extern __shared__ float smem[];
    float* W_s    = smem;                                  // [300][40] tf32-rounded
    float* cards  = smem + WS_FLOATS;                      // [32][300]
    float* apbuf  = cards + CARDS_FLOATS;                  // [32][36]
    const int tid  = threadIdx.x;
    const int lane = tid & 31;
    const int warp = tid >> 5;
    float* pw   = apbuf + AP_FLOATS + warp * PW_WORDS;
    int*   widx = (int*)pw;                                // [40]
    float* scw  = pw + IDXCAP;                             // [40]

    const uint32_t cards_u32 = (uint32_t)__cvta_generic_to_shared(cards);

    // ---- stage cards of group g into smem (cp.async.cg, L1-bypass) ----
    auto stage = [&](int g) {
        const float* gb = X + (size_t)g * GROUP * XSTRIDE + C_COLS;
        #pragma unroll 1
        for (int t = 0; t < 10; t++) {
            int idx = tid + THREADS * t;                   // 0..2559; valid < 2400
            if (idx < GROUP * 75) {
                int row = idx / 75, ch = idx - row * 75;
                cp16(cards_u32 + (uint32_t)(row * CS + ch * 4) * 4,
                     gb + (size_t)row * XSTRIDE + ch * 4);
            }
        }
        cp_commit();
    };

    int g = blockIdx.x;
    stage(g);                                              // GRID < NGROUPS always

    // ---- stage W into smem, rounded to tf32 (rna) ----
    for (int e = tid; e < C_COLS * A_DIM; e += THREADS) {
        int k = e >> 5, c = e & 31;
        W_s[k * WSTR + c] = __uint_as_float(f2tf32(W[e]));
    }

    const unsigned FULL   = 0xffffffffu;
    const unsigned ltmask = (1u << lane) - 1u;
    const int rt = warp & 1;                               // phase-1 row tile (16 rows)
    const int nt = warp >> 1;                              // phase-1 n tile (8 cols)
    const int gq = lane >> 2, tq = lane & 3;               // mma fragment coords
    const int qid = lane >> 3;                             // phase-2 octets
    const int sub = lane & 7;

    for (; g < NGROUPS; g += GRID) {
        cp_wait0();
        __syncthreads();                                   // cards ready; ap free

        // ---------- phase 1: ap = cards @ W + 1  (tf32 mma.sync) ----------
        {
            float d0 = 0.f, d1 = 0.f, d2 = 0.f, d3 = 0.f;
            const float* A0 = cards + (rt * 16 + gq) * CS;
            const float* A1 = A0 + 8 * CS;
            const float* Bp = W_s + nt * 8 + gq;
            #pragma unroll
            for (int kk = 0; kk < 37; kk++) {
                const int k0 = kk * 8;
                uint32_t a0 = __float_as_uint(A0[k0 + tq]);
                uint32_t a1 = __float_as_uint(A1[k0 + tq]);
                uint32_t a2 = __float_as_uint(A0[k0 + tq + 4]);
                uint32_t a3 = __float_as_uint(A1[k0 + tq + 4]);
                uint32_t b0 = __float_as_uint(Bp[(k0 + tq) * WSTR]);
                uint32_t b1 = __float_as_uint(Bp[(k0 + tq + 4) * WSTR]);
                mma_k8(d0, d1, d2, d3, a0, a1, a2, a3, b0, b1);
            }
            {   // K tail 296..299 (k4)
                uint32_t a0 = __float_as_uint(A0[296 + tq]);
                uint32_t a1 = __float_as_uint(A1[296 + tq]);
                uint32_t b0 = __float_as_uint(Bp[(296 + tq) * WSTR]);
                mma_k4(d0, d1, d2, d3, a0, a1, b0);
            }
            float* ap0 = apbuf + (rt * 16 + gq) * APS + nt * 8 + 2 * tq;
            *(float2*)ap0             = make_float2(d0 + 1.f, d1 + 1.f);
            *(float2*)(ap0 + 8 * APS) = make_float2(d2 + 1.f, d3 + 1.f);
        }
        __syncthreads();                                   // ap ready; cards free

        if (g + GRID < NGROUPS) stage(g + GRID);           // prefetch overlaps phase 2

        // ---------- phase 2: 4 rows/warp, sparse scores + masked log-softmax ----------
        #pragma unroll 1
        for (int i = 0; i < 4; i++) {
            const int lrow = warp * 4 + i;                 // group-local row
            const int grow = g * GROUP + lrow;             // global row

            // compaction of nonzero option columns
            const float4* osrc = (const float4*)(X + (size_t)grow * XSTRIDE);
            float4 ovv[3];
            ovv[0] = osrc[lane];
            ovv[1] = (lane + 32 < 75) ? osrc[lane + 32] : make_float4(0,0,0,0);
            ovv[2] = (lane + 64 < 75) ? osrc[lane + 64] : make_float4(0,0,0,0);
            int cn = 0;
            #pragma unroll
            for (int t = 0; t < 3; t++) {
                float vals[4] = {ovv[t].x, ovv[t].y, ovv[t].z, ovv[t].w};
                #pragma unroll
                for (int j = 0; j < 4; j++) {
                    bool f = (vals[j] != 0.0f);
                    unsigned mm = __ballot_sync(FULL, f);
                    if (f) {
                        int pos = cn + __popc(mm & ltmask);
                        if (pos < IDXCAP) widx[pos] = 4 * (lane + 32 * t) + j;
                    }
                    cn += __popc(mm);
                }
            }
            if (cn > IDXCAP) cn = IDXCAP;
            __syncwarp();

            // scores: 8 lanes per column, 4 columns in flight (W fp32 from global, L1-hot)
            float4 av = *(const float4*)(apbuf + lrow * APS + sub * 4);
            const int nch = (cn + 3) >> 2;
            #pragma unroll 2
            for (int ch = 0; ch < nch; ch++) {
                int  j   = ch * 4 + qid;
                bool val = j < cn;
                int  c   = val ? widx[j] : 0;
                float4 wv = *(const float4*)(W + c * A_DIM + sub * 4);
                float p = av.x * wv.x + av.y * wv.y + av.z * wv.z + av.w * wv.w;
                p += __shfl_xor_sync(FULL, p, 1);
                p += __shfl_xor_sync(FULL, p, 2);
                p += __shfl_xor_sync(FULL, p, 4);
                if (val && sub == 0) scw[j] = p;
            }
            __syncwarp();

            // masked log-softmax (zeros always present in the row)
            int  j0 = lane, j1 = lane + 32;
            bool v0 = j0 < cn, v1 = j1 < cn;
            float s0 = v0 ? scw[j0] : 0.0f;
            float s1 = v1 ? scw[j1] : 0.0f;
            int   c0 = v0 ? widx[j0] : -1;
            int   c1 = v1 ? widx[j1] : -1;

            float m = fmaxf(fmaxf(s0, s1), 0.0f);
            #pragma unroll
            for (int o = 16; o > 0; o >>= 1) m = fmaxf(m, __shfl_xor_sync(FULL, m, o));

            float g0 = (s0 > 0.f) ? 1.f : ((s0 < 0.f) ? -1.f : 0.f);
            float g1 = (s1 > 0.f) ? 1.f : ((s1 < 0.f) ? -1.f : 0.f);
            float sum = g0 * __expf(s0 - m * g0) + g1 * __expf(s1 - m * g1);
            #pragma unroll
            for (int o = 16; o > 0; o >>= 1) sum += __shfl_xor_sync(FULL, sum, o);
            float lse = __logf(sum);

            float* orow = Out + (size_t)grow * C_COLS;
            #pragma unroll
            for (int t = 0; t < 3; t++) {
                int gi = lane + 32 * t;
                if (gi < 75) *(float4*)(orow + 4 * gi) = make_float4(0.f, 0.f, 0.f, 0.f);
            }
            __syncwarp();
            if (c0 >= 0) orow[c0] = g0 * ((s0 - m * g0) - lse);
            if (c1 >= 0) orow[c1] = g1 * ((s1 - m * g1) - lse);
            __syncwarp();
        }
    }
}

extern "C" void kernel_launch(void* const* d_in, const int* in_sizes, int n_in,
                              void* d_out, int out_size)
{
    const float* X = (const float*)d_in[0];
    const float* W = (const float*)d_in[1];
    if (n_in >= 2 && in_sizes[0] < in_sizes[1]) {   // defensively order by size
        const float* t = X; X = W; W = t;
    }
    float* Out = (float*)d_out;

    cudaFuncSetAttribute(draftbot_kernel,
                         cudaFuncAttributeMaxDynamicSharedMemorySize, SMEM_BYTES);
    draftbot_kernel<<<GRID, THREADS, SMEM_BYTES>>>(X, W, Out);
}

// round 9
// speedup vs baseline: 2.4278x; 1.1647x over previous
#include <cuda_runtime.h>
#include <cstdint>

// Problem constants
#define B_ROWS   65536
#define C_COLS   300
#define A_DIM    32
#define XSTRIDE  600

#define THREADS  256
#define NWARPS   8
#define GROUP    32
#define NGROUPS  (B_ROWS / GROUP)        // 2048
#define GRID     592                     // 4 CTAs/SM

#define IDXCAP   40

// packed half2 layouts (uint32 words)
#define WPS      40                      // Wp stride: banks 8tq+gq distinct
#define CPS      156                     // cardsp stride: banks 28gq+tq distinct
#define APS      36                      // apbuf stride (floats)

#define WP_WORDS    (152 * WPS)          // 6080  (kp 0..151, k up to 303 zero-padded)
#define CP_WORDS    (GROUP * CPS)        // 4992
#define AP_WORDS    (GROUP * APS)        // 1152
#define PW_WORDS    96
#define SMEM_WORDS  (WP_WORDS + CP_WORDS + AP_WORDS + NWARPS * PW_WORDS)  // 13056
#define SMEM_BYTES  (SMEM_WORDS * 4)     // 52224 -> 4 CTAs/SM

__device__ __forceinline__ uint32_t pack_f16x2(float lo, float hi) {
    uint32_t r;                          // d.hi = first src, d.lo = second src
    asm("cvt.rn.f16x2.f32 %0, %1, %2;" : "=r"(r) : "f"(hi), "f"(lo));
    return r;
}
__device__ __forceinline__ void mma_f16_k16(float& d0, float& d1, float& d2, float& d3,
                                            uint32_t a0, uint32_t a1, uint32_t a2, uint32_t a3,
                                            uint32_t b0, uint32_t b1) {
    asm("mma.sync.aligned.m16n8k16.row.col.f32.f16.f16.f32 "
        "{%0,%1,%2,%3},{%4,%5,%6,%7},{%8,%9},{%0,%1,%2,%3};"
        : "+f"(d0), "+f"(d1), "+f"(d2), "+f"(d3)
        : "r"(a0), "r"(a1), "r"(a2), "r"(a3), "r"(b0), "r"(b1));
}

__global__ __launch_bounds__(THREADS, 4)
void draftbot_kernel(const float* __restrict__ X,
                     const float* __restrict__ W,
                     float* __restrict__ Out)
{
    extern __shared__ uint32_t smw[];
    uint32_t* Wp     = smw;                          // [152][40] half2 (k-pairs x a)
    uint32_t* cardsp = smw + WP_WORDS;               // [32][156] half2 (row x k-pairs)
    float*    apbuf  = (float*)(smw + WP_WORDS + CP_WORDS);  // [32][36]
    const int tid  = threadIdx.x;
    const int lane = tid & 31;
    const int warp = tid >> 5;
    float* pw   = apbuf + AP_WORDS + warp * PW_WORDS;
    int*   widx = (int*)pw;                          // [40]
    float* scw  = pw + IDXCAP;                       // [40]

    // ---- one-time init: Wp (fp16-packed W, zero-padded to kp<152) + cardsp pads ----
    for (int i = tid; i < 152 * 32; i += THREADS) {
        int kp = i >> 5, a = i & 31;
        float lo = (2 * kp     < C_COLS) ? W[(2 * kp)     * A_DIM + a] : 0.0f;
        float hi = (2 * kp + 1 < C_COLS) ? W[(2 * kp + 1) * A_DIM + a] : 0.0f;
        Wp[kp * WPS + a] = pack_f16x2(lo, hi);
    }
    for (int i = tid; i < GROUP * 2; i += THREADS) {         // cardsp kp 150,151 = 0
        int r = i >> 1, kp = 150 + (i & 1);
        cardsp[r * CPS + kp] = 0u;
    }

    const unsigned FULL   = 0xffffffffu;
    const unsigned ltmask = (1u << lane) - 1u;
    const int rt = warp & 1;                         // phase-1 row tile (16 rows)
    const int nt = warp >> 1;                        // phase-1 n tile (8 cols)
    const int gq = lane >> 2, tq = lane & 3;         // mma fragment coords
    const int qid = lane >> 3;                       // phase-2 octets
    const int sub = lane & 7;

    for (int g = blockIdx.x; g < NGROUPS; g += GRID) {
        __syncthreads();                             // prev phase-2 done; cardsp free

        // ---------- stage cards of group g, converting f32 -> f16x2 ----------
        {
            const float* gb = X + (size_t)g * GROUP * XSTRIDE + C_COLS;
            #pragma unroll 1
            for (int t = 0; t < 10; t++) {
                int idx = tid + THREADS * t;         // 0..2559; valid < 2400
                if (idx < GROUP * 75) {
                    int row = idx / 75, ch = idx - row * 75;
                    float4 v = *(const float4*)(gb + (size_t)row * XSTRIDE + 4 * ch);
                    uint2 h;
                    h.x = pack_f16x2(v.x, v.y);
                    h.y = pack_f16x2(v.z, v.w);
                    *(uint2*)(cardsp + row * CPS + 2 * ch) = h;
                }
            }
        }
        __syncthreads();                             // cardsp ready

        // ---------- phase 1: ap = cards @ W + 1  (fp16 m16n8k16) ----------
        {
            float d0 = 0.f, d1 = 0.f, d2 = 0.f, d3 = 0.f;
            const uint32_t* A0 = cardsp + (rt * 16 + gq) * CPS;
            const uint32_t* A1 = A0 + 8 * CPS;
            const uint32_t* Bp = Wp + nt * 8 + gq;
            #pragma unroll
            for (int kk = 0; kk < 19; kk++) {        // 19 * k16 = 304 (padded)
                const int kp0 = kk * 8;
                uint32_t a0 = A0[kp0 + tq];
                uint32_t a1 = A1[kp0 + tq];
                uint32_t a2 = A0[kp0 + tq + 4];
                uint32_t a3 = A1[kp0 + tq + 4];
                uint32_t b0 = Bp[(kp0 + tq) * WPS];
                uint32_t b1 = Bp[(kp0 + tq + 4) * WPS];
                mma_f16_k16(d0, d1, d2, d3, a0, a1, a2, a3, b0, b1);
            }
            float* ap0 = apbuf + (rt * 16 + gq) * APS + nt * 8 + 2 * tq;
            *(float2*)ap0             = make_float2(d0 + 1.f, d1 + 1.f);
            *(float2*)(ap0 + 8 * APS) = make_float2(d2 + 1.f, d3 + 1.f);
        }
        __syncthreads();                             // ap ready

        // ---------- phase 2: 4 rows/warp, sparse scores + masked log-softmax ----------
        #pragma unroll 1
        for (int i = 0; i < 4; i++) {
            const int lrow = warp * 4 + i;
            const int grow = g * GROUP + lrow;

            // compaction of nonzero option columns
            const float4* osrc = (const float4*)(X + (size_t)grow * XSTRIDE);
            float4 ovv[3];
            ovv[0] = osrc[lane];
            ovv[1] = (lane + 32 < 75) ? osrc[lane + 32] : make_float4(0,0,0,0);
            ovv[2] = (lane + 64 < 75) ? osrc[lane + 64] : make_float4(0,0,0,0);
            int cn = 0;
            #pragma unroll
            for (int t = 0; t < 3; t++) {
                float vals[4] = {ovv[t].x, ovv[t].y, ovv[t].z, ovv[t].w};
                #pragma unroll
                for (int j = 0; j < 4; j++) {
                    bool f = (vals[j] != 0.0f);
                    unsigned mm = __ballot_sync(FULL, f);
                    if (f) {
                        int pos = cn + __popc(mm & ltmask);
                        if (pos < IDXCAP) widx[pos] = 4 * (lane + 32 * t) + j;
                    }
                    cn += __popc(mm);
                }
            }
            if (cn > IDXCAP) cn = IDXCAP;
            __syncwarp();

            // scores: 8 lanes per column, 4 columns in flight (W fp32 global, L1-hot)
            float4 av = *(const float4*)(apbuf + lrow * APS + sub * 4);
            const int nch = (cn + 3) >> 2;
            #pragma unroll 2
            for (int ch = 0; ch < nch; ch++) {
                int  j   = ch * 4 + qid;
                bool val = j < cn;
                int  c   = val ? widx[j] : 0;
                float4 wv = *(const float4*)(W + c * A_DIM + sub * 4);
                float p = av.x * wv.x + av.y * wv.y + av.z * wv.z + av.w * wv.w;
                p += __shfl_xor_sync(FULL, p, 1);
                p += __shfl_xor_sync(FULL, p, 2);
                p += __shfl_xor_sync(FULL, p, 4);
                if (val && sub == 0) scw[j] = p;
            }
            __syncwarp();

            // masked log-softmax (zeros always present in the row)
            int  j0 = lane, j1 = lane + 32;
            bool v0 = j0 < cn, v1 = j1 < cn;
            float s0 = v0 ? scw[j0] : 0.0f;
            float s1 = v1 ? scw[j1] : 0.0f;
            int   c0 = v0 ? widx[j0] : -1;
            int   c1 = v1 ? widx[j1] : -1;

            float m = fmaxf(fmaxf(s0, s1), 0.0f);
            #pragma unroll
            for (int o = 16; o > 0; o >>= 1) m = fmaxf(m, __shfl_xor_sync(FULL, m, o));

            float g0 = (s0 > 0.f) ? 1.f : ((s0 < 0.f) ? -1.f : 0.f);
            float g1 = (s1 > 0.f) ? 1.f : ((s1 < 0.f) ? -1.f : 0.f);
            float sum = g0 * __expf(s0 - m * g0) + g1 * __expf(s1 - m * g1);
            #pragma unroll
            for (int o = 16; o > 0; o >>= 1) sum += __shfl_xor_sync(FULL, sum, o);
            float lse = __logf(sum);

            float* orow = Out + (size_t)grow * C_COLS;
            #pragma unroll
            for (int t = 0; t < 3; t++) {
                int gi = lane + 32 * t;
                if (gi < 75) *(float4*)(orow + 4 * gi) = make_float4(0.f, 0.f, 0.f, 0.f);
            }
            __syncwarp();
            if (c0 >= 0) orow[c0] = g0 * ((s0 - m * g0) - lse);
            if (c1 >= 0) orow[c1] = g1 * ((s1 - m * g1) - lse);
            __syncwarp();
        }
    }
}

extern "C" void kernel_launch(void* const* d_in, const int* in_sizes, int n_in,
                              void* d_out, int out_size)
{
    const float* X = (const float*)d_in[0];
    const float* W = (const float*)d_in[1];
    if (n_in >= 2 && in_sizes[0] < in_sizes[1]) {   // defensively order by size
        const float* t = X; X = W; W = t;
    }
    float* Out = (float*)d_out;

    cudaFuncSetAttribute(draftbot_kernel,
                         cudaFuncAttributeMaxDynamicSharedMemorySize, SMEM_BYTES);
    draftbot_kernel<<<GRID, THREADS, SMEM_BYTES>>>(X, W, Out);
}